// round 3
// baseline (speedup 1.0000x reference)
#include <cuda_runtime.h>
#include <math.h>

// ---------------------------------------------------------------------------
// Problem constants
//   ARCH = (1024, 2048, 2048, 512), BATCH = 4096, STEPS = 20, LR = 0.1
// Inputs (metadata order): x, W0, b0, W1, b1, W2, b2
// Output: r3 (4096*512 floats) followed by total_error scalar.
// ---------------------------------------------------------------------------

#define MB      4096
#define D0      1024
#define D1      2048
#define D2      2048
#define D3      512
#define NSTEPS  20
#define LRC     0.1f

// Scratch state (device globals -- allocation-free per harness rules)
__device__ float g_r1[(size_t)MB * D1];
__device__ float g_r2[(size_t)MB * D2];
__device__ float g_r3[(size_t)MB * D3];
__device__ float g_e0[(size_t)MB * D0];
__device__ float g_e1[(size_t)MB * D1];
__device__ float g_e2[(size_t)MB * D2];
__device__ float g_part[4096];

// ---------------------------------------------------------------------------
// Tiled FP32 GEMM, 128x128x16 tile, 8x8 per thread, 256 threads.
//   BNT = true : C[m,n] = sum_k A[m,k] * B[n,k]   (B row-major N x K, "NT")
//   BNT = false: C[m,n] = sum_k A[m,k] * B[k,n]   (B row-major K x N, "NN")
// Epilogues:
//   EPI 0: D = tanh(acc + X[n])            (X = bias, length N)
//   EPI 1: D = X - tanh(acc)               (X = prev state, M x N)
//   EPI 2: D = D + LR * (acc - X)          (X = error, M x N; D updated in place)
// All dims are multiples of 128 -> no bounds checks.
// ---------------------------------------------------------------------------
#define BMt 128
#define BNt 128
#define BKt 16
#define TMt 8
#define TNt 8

template <bool BNT, int EPI>
__global__ __launch_bounds__(256, 2)
void gemm_k(const float* __restrict__ A, const float* __restrict__ B,
            const float* X, float* D, int M, int N, int K)
{
    __shared__ float As[BKt][BMt + 4];
    __shared__ float Bs[BKt][BNt + 4];

    const int tid = threadIdx.x;
    const int bm  = blockIdx.y * BMt;
    const int bn  = blockIdx.x * BNt;

    const int row_t = (tid >> 4) * TMt;   // 0..120
    const int col_t = (tid & 15) * TNt;   // 0..120

    const int la_r = tid >> 2;            // 0..63 (k-contiguous tile loads)
    const int la_c = (tid & 3) << 2;      // 0,4,8,12
    const int lb_r = tid >> 5;            // 0..7  (NN: n-contiguous tile loads)
    const int lb_c = (tid & 31) << 2;     // 0..124

    float acc[TMt][TNt] = {};

    for (int k0 = 0; k0 < K; k0 += BKt) {
        // --- load A tile (M x K, k-contiguous), transpose into As[k][m]
#pragma unroll
        for (int i = 0; i < 2; i++) {
            int r = la_r + i * 64;
            float4 v = *reinterpret_cast<const float4*>(
                &A[(size_t)(bm + r) * K + k0 + la_c]);
            As[la_c + 0][r] = v.x;
            As[la_c + 1][r] = v.y;
            As[la_c + 2][r] = v.z;
            As[la_c + 3][r] = v.w;
        }
        // --- load B tile
        if (BNT) {
#pragma unroll
            for (int i = 0; i < 2; i++) {
                int r = la_r + i * 64;
                float4 v = *reinterpret_cast<const float4*>(
                    &B[(size_t)(bn + r) * K + k0 + la_c]);
                Bs[la_c + 0][r] = v.x;
                Bs[la_c + 1][r] = v.y;
                Bs[la_c + 2][r] = v.z;
                Bs[la_c + 3][r] = v.w;
            }
        } else {
#pragma unroll
            for (int i = 0; i < 2; i++) {
                int r = lb_r + i * 8;
                float4 v = *reinterpret_cast<const float4*>(
                    &B[(size_t)(k0 + r) * N + bn + lb_c]);
                *reinterpret_cast<float4*>(&Bs[r][lb_c]) = v;
            }
        }
        __syncthreads();

#pragma unroll
        for (int kk = 0; kk < BKt; kk++) {
            float a[TMt], b[TNt];
#pragma unroll
            for (int i = 0; i < TMt; i++) a[i] = As[kk][row_t + i];
#pragma unroll
            for (int j = 0; j < TNt; j++) b[j] = Bs[kk][col_t + j];
#pragma unroll
            for (int i = 0; i < TMt; i++)
#pragma unroll
                for (int j = 0; j < TNt; j++)
                    acc[i][j] = fmaf(a[i], b[j], acc[i][j]);
        }
        __syncthreads();
    }

    // --- epilogue (vectorized; all offsets 32B-aligned)
    float xb[TNt];
    if (EPI == 0) {
#pragma unroll
        for (int j = 0; j < TNt; j++) xb[j] = X[bn + col_t + j];
    }

#pragma unroll
    for (int i = 0; i < TMt; i++) {
        size_t idx = (size_t)(bm + row_t + i) * N + bn + col_t;
        float out[TNt];
        if (EPI == 0) {
#pragma unroll
            for (int j = 0; j < TNt; j++) out[j] = tanhf(acc[i][j] + xb[j]);
        } else if (EPI == 1) {
            float4 x0 = *reinterpret_cast<const float4*>(&X[idx]);
            float4 x1 = *reinterpret_cast<const float4*>(&X[idx + 4]);
            float xs[8] = {x0.x, x0.y, x0.z, x0.w, x1.x, x1.y, x1.z, x1.w};
#pragma unroll
            for (int j = 0; j < TNt; j++) out[j] = xs[j] - tanhf(acc[i][j]);
        } else {
            float4 x0 = *reinterpret_cast<const float4*>(&X[idx]);
            float4 x1 = *reinterpret_cast<const float4*>(&X[idx + 4]);
            float4 d0 = *reinterpret_cast<const float4*>(&D[idx]);
            float4 d1 = *reinterpret_cast<const float4*>(&D[idx + 4]);
            float xs[8] = {x0.x, x0.y, x0.z, x0.w, x1.x, x1.y, x1.z, x1.w};
            float ds[8] = {d0.x, d0.y, d0.z, d0.w, d1.x, d1.y, d1.z, d1.w};
#pragma unroll
            for (int j = 0; j < TNt; j++)
                out[j] = ds[j] + LRC * (acc[i][j] - xs[j]);
        }
        float4 o0 = make_float4(out[0], out[1], out[2], out[3]);
        float4 o1 = make_float4(out[4], out[5], out[6], out[7]);
        *reinterpret_cast<float4*>(&D[idx])     = o0;
        *reinterpret_cast<float4*>(&D[idx + 4]) = o1;
    }
}

// ---------------------------------------------------------------------------
// Copy r3 -> d_out (float4)
// ---------------------------------------------------------------------------
__global__ void copy_k(const float* __restrict__ s, float* __restrict__ d, int n4)
{
    int i = blockIdx.x * blockDim.x + threadIdx.x;
    if (i < n4)
        reinterpret_cast<float4*>(d)[i] =
            reinterpret_cast<const float4*>(s)[i];
}

// ---------------------------------------------------------------------------
// Deterministic two-stage sum-of-squares
// ---------------------------------------------------------------------------
__global__ void sumsq_partial(const float* __restrict__ x, long long n,
                              float* __restrict__ part)
{
    float s = 0.f;
    long long stride = (long long)gridDim.x * blockDim.x;
    for (long long i = (long long)blockIdx.x * blockDim.x + threadIdx.x;
         i < n; i += stride) {
        float v = x[i];
        s = fmaf(v, v, s);
    }
    __shared__ float sh[256];
    sh[threadIdx.x] = s;
    __syncthreads();
    for (int o = 128; o > 0; o >>= 1) {
        if (threadIdx.x < o) sh[threadIdx.x] += sh[threadIdx.x + o];
        __syncthreads();
    }
    if (threadIdx.x == 0) part[blockIdx.x] = sh[0];
}

__global__ void finalize_k(const float* __restrict__ part, int n,
                           float* __restrict__ out)
{
    float s = 0.f;
    for (int i = threadIdx.x; i < n; i += 256) s += part[i];
    __shared__ float sh[256];
    sh[threadIdx.x] = s;
    __syncthreads();
    for (int o = 128; o > 0; o >>= 1) {
        if (threadIdx.x < o) sh[threadIdx.x] += sh[threadIdx.x + o];
        __syncthreads();
    }
    if (threadIdx.x == 0) out[0] = 0.5f * sh[0];
}

// ---------------------------------------------------------------------------
// Launch
// ---------------------------------------------------------------------------
static inline dim3 ggrid(int M, int N) { return dim3(N / BNt, M / BMt); }

extern "C" void kernel_launch(void* const* d_in, const int* in_sizes, int n_in,
                              void* d_out, int out_size)
{
    const float* x  = (const float*)d_in[0];
    const float* W0 = (const float*)d_in[1];
    const float* b0 = (const float*)d_in[2];
    const float* W1 = (const float*)d_in[3];
    const float* b1 = (const float*)d_in[4];
    const float* W2 = (const float*)d_in[5];
    const float* b2 = (const float*)d_in[6];
    float* out = (float*)d_out;

    float *r1, *r2, *r3, *e0, *e1, *e2, *part;
    cudaGetSymbolAddress((void**)&r1,  g_r1);
    cudaGetSymbolAddress((void**)&r2,  g_r2);
    cudaGetSymbolAddress((void**)&r3,  g_r3);
    cudaGetSymbolAddress((void**)&e0,  g_e0);
    cudaGetSymbolAddress((void**)&e1,  g_e1);
    cudaGetSymbolAddress((void**)&e2,  g_e2);
    cudaGetSymbolAddress((void**)&part, g_part);

    const dim3 blk(256);

    // ---- feedforward init: r_{i+1} = tanh(r_i @ W_i^T + b_i)
    gemm_k<true, 0><<<ggrid(MB, D1), blk>>>(x,  W0, b0, r1, MB, D1, D0);
    gemm_k<true, 0><<<ggrid(MB, D2), blk>>>(r1, W1, b1, r2, MB, D2, D1);
    gemm_k<true, 0><<<ggrid(MB, D3), blk>>>(r2, W2, b2, r3, MB, D3, D2);

    // ---- 20 PC inference steps
    for (int s = 0; s < NSTEPS; s++) {
        // errors from current states
        gemm_k<false, 1><<<ggrid(MB, D2), blk>>>(r3, W2, r2, e2, MB, D2, D3);
        gemm_k<false, 1><<<ggrid(MB, D1), blk>>>(r2, W1, r1, e1, MB, D1, D2);
        gemm_k<false, 1><<<ggrid(MB, D0), blk>>>(r1, W0, x,  e0, MB, D0, D1);
        // state updates: r_i += LR * (e_{i-1} @ W_{i-1}^T - e_i)
        gemm_k<true, 2><<<ggrid(MB, D1), blk>>>(e0, W0, e1, r1, MB, D1, D0);
        gemm_k<true, 2><<<ggrid(MB, D2), blk>>>(e1, W1, e2, r2, MB, D2, D1);
        gemm_k<true, 2><<<ggrid(MB, D3), blk>>>(e2, W2, r3, r3, MB, D3, D2);
    }

    // ---- final errors (for total_error)
    gemm_k<false, 1><<<ggrid(MB, D2), blk>>>(r3, W2, r2, e2, MB, D2, D3);
    gemm_k<false, 1><<<ggrid(MB, D1), blk>>>(r2, W1, r1, e1, MB, D1, D2);
    gemm_k<false, 1><<<ggrid(MB, D0), blk>>>(r1, W0, x,  e0, MB, D0, D1);

    // ---- output r3
    const int n_r3 = MB * D3;              // 2097152
    copy_k<<<(n_r3 / 4 + 255) / 256, 256>>>(r3, out, n_r3 / 4);

    // ---- total_error = 0.5 * (|e0|^2 + |e1|^2 + |e2|^2 + |r3|^2)
    sumsq_partial<<<1024, 256>>>(e0, (long long)MB * D0, part + 0);
    sumsq_partial<<<1024, 256>>>(e1, (long long)MB * D1, part + 1024);
    sumsq_partial<<<1024, 256>>>(e2, (long long)MB * D2, part + 2048);
    sumsq_partial<<<1024, 256>>>(r3, (long long)MB * D3, part + 3072);
    finalize_k<<<1, 256>>>(part, 4096, out + (out_size - 1));
}

// round 5
// speedup vs baseline: 2.2542x; 2.2542x over previous
#include <cuda_runtime.h>
#include <cstdint>
#include <math.h>

// ---------------------------------------------------------------------------
// PcLinearBlock: ARCH=(1024,2048,2048,512), BATCH=4096, STEPS=20, LR=0.1
// Inputs: x, W0, b0, W1, b1, W2, b2. Output: r3 (4096x512) + total_error.
// tf32 mma.sync (m16n8k8) GEMM, 128x128x32 tile, cp.async 3-stage pipeline.
// (tcgen05 is unavailable: harness PTX target is base sm_103, no 'a' suffix.)
// ---------------------------------------------------------------------------

#define MB 4096
#define D0 1024
#define D1 2048
#define D2 2048
#define D3 512
#define NSTEPS 20
#define LRC 0.1f

// ---- scratch (device globals; allocation-free) ----
__device__ __align__(128) float g_r1[(size_t)MB * D1];
__device__ __align__(128) float g_r2[(size_t)MB * D2];
__device__ __align__(128) float g_r3[(size_t)MB * D3];
__device__ __align__(128) float g_e0[(size_t)MB * D0];
__device__ __align__(128) float g_e1[(size_t)MB * D1];
__device__ __align__(128) float g_e2[(size_t)MB * D2];
__device__ __align__(128) float g_Wt0[(size_t)D0 * D1];
__device__ __align__(128) float g_Wt1[(size_t)D1 * D2];
__device__ __align__(128) float g_Wt2[(size_t)D2 * D3];
__device__ float g_part[4096];

// ---------------------------------------------------------------------------
// helpers
// ---------------------------------------------------------------------------
__device__ __forceinline__ uint32_t s2u(const void* p) {
    uint32_t a;
    asm("{ .reg .u64 t; cvta.to.shared.u64 t, %1; cvt.u32.u64 %0, t; }"
        : "=r"(a) : "l"(p));
    return a;
}

__device__ __forceinline__ void cp16(uint32_t dst, const void* src) {
    asm volatile("cp.async.cg.shared.global [%0], [%1], 16;"
                 :: "r"(dst), "l"(src));
}

__device__ __forceinline__ float ldsf(uint32_t addr) {
    float v;
    asm volatile("ld.shared.f32 %0, [%1];" : "=f"(v) : "r"(addr));
    return v;
}

__device__ __forceinline__ uint32_t f2tf32(float f) {
    uint32_t u;
    asm("cvt.rna.tf32.f32 %0, %1;" : "=r"(u) : "f"(f));
    return u;
}

__device__ __forceinline__ void mma8(float* c, const uint32_t* a,
                                     const uint32_t* b) {
    asm volatile(
        "mma.sync.aligned.m16n8k8.row.col.f32.tf32.tf32.f32 "
        "{%0,%1,%2,%3}, {%4,%5,%6,%7}, {%8,%9}, {%0,%1,%2,%3};"
        : "+f"(c[0]), "+f"(c[1]), "+f"(c[2]), "+f"(c[3])
        : "r"(a[0]), "r"(a[1]), "r"(a[2]), "r"(a[3]), "r"(b[0]), "r"(b[1]));
}

// exact algebraic tanh: (e^{2x}-1)/(e^{2x}+1); saturates correctly.
__device__ __forceinline__ float fast_tanh(float x) {
    float e = __expf(2.0f * x);
    return 1.0f - 2.0f / (e + 1.0f);
}

// ---------------------------------------------------------------------------
// tf32 GEMM:  C[m,n] = sum_k A[m,k] * B[n,k]   (A MxK, B NxK, both K-major)
// CTA tile 128x128x32, 256 threads (8 warps, warp tile 64x32).
// Smem stage: A 128x36 fp32 (18432 B) + B 128x36 (18432 B); 3 stages.
// EPI 0: D = tanh(acc + X[n])      (X = bias)
// EPI 1: D = X - tanh(acc)         (X = prev state, MxN)
// EPI 2: D = D + LR*(acc - X)      (X = error, MxN; in place)
// ---------------------------------------------------------------------------
#define STG_B   36864            // bytes per stage (A+B)
#define SMEM_SZ (3 * STG_B)      // 110592

template <int EPI>
__global__ void __launch_bounds__(256, 2)
tc_gemm(const float* __restrict__ A, const float* __restrict__ B,
        const float* __restrict__ X, float* __restrict__ D, int N, int K)
{
    extern __shared__ char smem[];
    const uint32_t sb = s2u(smem);
    const int tid = threadIdx.x;
    const int wid = tid >> 5, lane = tid & 31;
    const int gid = lane >> 2, tig = lane & 3;
    const int warp_m = wid & 1;       // 0..1 -> 64 rows each
    const int warp_n = wid >> 1;      // 0..3 -> 32 cols each
    const int bm = blockIdx.y * 128, bn = blockIdx.x * 128;

    // global->smem copy mapping: thread t copies 64B (4x16B) of row t/2
    const int ar = tid >> 1;
    const float* gA = A + (size_t)(bm + ar) * K + (tid & 1) * 16;
    const float* gB = B + (size_t)(bn + ar) * K + (tid & 1) * 16;
    const uint32_t soff = (uint32_t)(ar * 144 + (tid & 1) * 64);

    const int KT = K >> 5;            // 32-float K chunks

    // ---- prologue: prefetch stages 0..2
#pragma unroll
    for (int kt = 0; kt < 3; kt++) {
        uint32_t base = sb + kt * STG_B;
        const float* pa = gA + kt * 32;
        const float* pb = gB + kt * 32;
#pragma unroll
        for (int i = 0; i < 4; i++) cp16(base + soff + i * 16, pa + i * 4);
#pragma unroll
        for (int i = 0; i < 4; i++)
            cp16(base + 18432 + soff + i * 16, pb + i * 4);
        asm volatile("cp.async.commit_group;" ::: "memory");
    }

    float acc[4][4][4];
#pragma unroll
    for (int mi = 0; mi < 4; mi++)
#pragma unroll
        for (int ni = 0; ni < 4; ni++)
#pragma unroll
            for (int r = 0; r < 4; r++) acc[mi][ni][r] = 0.f;

    // ---- mainloop
    for (int kt = 0; kt < KT; kt++) {
        asm volatile("cp.async.wait_group 2;" ::: "memory");
        __syncthreads();

        const int stg = kt % 3;
        const uint32_t sA = sb + stg * STG_B;
        const uint32_t sB = sA + 18432;

#pragma unroll
        for (int ks = 0; ks < 4; ks++) {
            uint32_t a[4][4], b[4][2];
#pragma unroll
            for (int mi = 0; mi < 4; mi++) {
                uint32_t ad = sA + (uint32_t)((warp_m * 64 + mi * 16 + gid) * 144
                                              + (ks * 8 + tig) * 4);
                a[mi][0] = f2tf32(ldsf(ad));
                a[mi][1] = f2tf32(ldsf(ad + 1152));   // +8 rows
                a[mi][2] = f2tf32(ldsf(ad + 16));     // +4 k
                a[mi][3] = f2tf32(ldsf(ad + 1168));
            }
#pragma unroll
            for (int ni = 0; ni < 4; ni++) {
                uint32_t bd = sB + (uint32_t)((warp_n * 32 + ni * 8 + gid) * 144
                                              + (ks * 8 + tig) * 4);
                b[ni][0] = f2tf32(ldsf(bd));
                b[ni][1] = f2tf32(ldsf(bd + 16));
            }
#pragma unroll
            for (int mi = 0; mi < 4; mi++)
#pragma unroll
                for (int ni = 0; ni < 4; ni++)
                    mma8(acc[mi][ni], a[mi], b[ni]);
        }

        __syncthreads();   // all warps done reading this stage
        const int kn = kt + 3;
        if (kn < KT) {
            uint32_t base = sb + stg * STG_B;
            const float* pa = gA + kn * 32;
            const float* pb = gB + kn * 32;
#pragma unroll
            for (int i = 0; i < 4; i++) cp16(base + soff + i * 16, pa + i * 4);
#pragma unroll
            for (int i = 0; i < 4; i++)
                cp16(base + 18432 + soff + i * 16, pb + i * 4);
        }
        asm volatile("cp.async.commit_group;" ::: "memory");
    }

    // ---- fused epilogue (accumulators in registers)
#pragma unroll
    for (int mi = 0; mi < 4; mi++) {
        const int gm = bm + warp_m * 64 + mi * 16 + gid;
#pragma unroll
        for (int ni = 0; ni < 4; ni++) {
            const int gn = bn + warp_n * 32 + ni * 8 + 2 * tig;
            const size_t i0 = (size_t)gm * N + gn;
            const size_t i1 = i0 + (size_t)8 * N;
            const float* c = acc[mi][ni];
            float2 o0, o1;
            if (EPI == 0) {
                float b0v = X[gn], b1v = X[gn + 1];
                o0.x = fast_tanh(c[0] + b0v);
                o0.y = fast_tanh(c[1] + b1v);
                o1.x = fast_tanh(c[2] + b0v);
                o1.y = fast_tanh(c[3] + b1v);
            } else if (EPI == 1) {
                float2 x0 = *reinterpret_cast<const float2*>(&X[i0]);
                float2 x1 = *reinterpret_cast<const float2*>(&X[i1]);
                o0.x = x0.x - fast_tanh(c[0]);
                o0.y = x0.y - fast_tanh(c[1]);
                o1.x = x1.x - fast_tanh(c[2]);
                o1.y = x1.y - fast_tanh(c[3]);
            } else {
                float2 x0 = *reinterpret_cast<const float2*>(&X[i0]);
                float2 x1 = *reinterpret_cast<const float2*>(&X[i1]);
                float2 d0 = *reinterpret_cast<const float2*>(&D[i0]);
                float2 d1 = *reinterpret_cast<const float2*>(&D[i1]);
                o0.x = d0.x + LRC * (c[0] - x0.x);
                o0.y = d0.y + LRC * (c[1] - x0.y);
                o1.x = d1.x + LRC * (c[2] - x1.x);
                o1.y = d1.y + LRC * (c[3] - x1.y);
            }
            *reinterpret_cast<float2*>(&D[i0]) = o0;
            *reinterpret_cast<float2*>(&D[i1]) = o1;
        }
    }
}

// ---------------------------------------------------------------------------
// Weight transpose: src (R x C) -> dst (C x R). R, C multiples of 32.
// ---------------------------------------------------------------------------
__global__ void transpose_k(const float* __restrict__ src,
                            float* __restrict__ dst, int R, int C)
{
    __shared__ float t[32][33];
    int bx = blockIdx.x * 32, by = blockIdx.y * 32;
    int x = bx + threadIdx.x;
#pragma unroll
    for (int i = 0; i < 32; i += 8)
        t[threadIdx.y + i][threadIdx.x] =
            src[(size_t)(by + threadIdx.y + i) * C + x];
    __syncthreads();
    int xo = by + threadIdx.x;
#pragma unroll
    for (int i = 0; i < 32; i += 8)
        dst[(size_t)(bx + threadIdx.y + i) * R + xo] =
            t[threadIdx.x][threadIdx.y + i];
}

// ---------------------------------------------------------------------------
// Output copy + deterministic two-stage sum-of-squares
// ---------------------------------------------------------------------------
__global__ void copy_k(const float* __restrict__ s, float* __restrict__ d,
                       int n4)
{
    int i = blockIdx.x * blockDim.x + threadIdx.x;
    if (i < n4)
        reinterpret_cast<float4*>(d)[i] =
            reinterpret_cast<const float4*>(s)[i];
}

__global__ void sumsq_partial(const float* __restrict__ x, long long n,
                              float* __restrict__ part)
{
    float s = 0.f;
    long long stride = (long long)gridDim.x * blockDim.x;
    for (long long i = (long long)blockIdx.x * blockDim.x + threadIdx.x;
         i < n; i += stride) {
        float v = x[i];
        s = fmaf(v, v, s);
    }
    __shared__ float sh[256];
    sh[threadIdx.x] = s;
    __syncthreads();
    for (int o = 128; o > 0; o >>= 1) {
        if (threadIdx.x < o) sh[threadIdx.x] += sh[threadIdx.x + o];
        __syncthreads();
    }
    if (threadIdx.x == 0) part[blockIdx.x] = sh[0];
}

__global__ void finalize_k(const float* __restrict__ part, int n,
                           float* __restrict__ out)
{
    float s = 0.f;
    for (int i = threadIdx.x; i < n; i += 256) s += part[i];
    __shared__ float sh[256];
    sh[threadIdx.x] = s;
    __syncthreads();
    for (int o = 128; o > 0; o >>= 1) {
        if (threadIdx.x < o) sh[threadIdx.x] += sh[threadIdx.x + o];
        __syncthreads();
    }
    if (threadIdx.x == 0) out[0] = 0.5f * sh[0];
}

// ---------------------------------------------------------------------------
// Launch
// ---------------------------------------------------------------------------
static inline dim3 ggrid(int N) { return dim3(N / 128, MB / 128); }

extern "C" void kernel_launch(void* const* d_in, const int* in_sizes, int n_in,
                              void* d_out, int out_size)
{
    const float* x  = (const float*)d_in[0];
    const float* W0 = (const float*)d_in[1];
    const float* b0 = (const float*)d_in[2];
    const float* W1 = (const float*)d_in[3];
    const float* b1 = (const float*)d_in[4];
    const float* W2 = (const float*)d_in[5];
    const float* b2 = (const float*)d_in[6];
    float* out = (float*)d_out;

    float *r1, *r2, *r3, *e0, *e1, *e2, *wt0, *wt1, *wt2, *part;
    cudaGetSymbolAddress((void**)&r1,  g_r1);
    cudaGetSymbolAddress((void**)&r2,  g_r2);
    cudaGetSymbolAddress((void**)&r3,  g_r3);
    cudaGetSymbolAddress((void**)&e0,  g_e0);
    cudaGetSymbolAddress((void**)&e1,  g_e1);
    cudaGetSymbolAddress((void**)&e2,  g_e2);
    cudaGetSymbolAddress((void**)&wt0, g_Wt0);
    cudaGetSymbolAddress((void**)&wt1, g_Wt1);
    cudaGetSymbolAddress((void**)&wt2, g_Wt2);
    cudaGetSymbolAddress((void**)&part, g_part);

    cudaFuncSetAttribute(tc_gemm<0>, cudaFuncAttributeMaxDynamicSharedMemorySize, SMEM_SZ);
    cudaFuncSetAttribute(tc_gemm<1>, cudaFuncAttributeMaxDynamicSharedMemorySize, SMEM_SZ);
    cudaFuncSetAttribute(tc_gemm<2>, cudaFuncAttributeMaxDynamicSharedMemorySize, SMEM_SZ);

    // ---- transpose weights once: Wt_i = W_i^T (K-major B for error GEMMs)
    transpose_k<<<dim3(D0 / 32, D1 / 32), dim3(32, 8)>>>(W0, wt0, D1, D0);
    transpose_k<<<dim3(D1 / 32, D2 / 32), dim3(32, 8)>>>(W1, wt1, D2, D1);
    transpose_k<<<dim3(D2 / 32, D3 / 32), dim3(32, 8)>>>(W2, wt2, D3, D2);

    // ---- feedforward init: r_{i+1} = tanh(r_i @ W_i^T + b_i)
    tc_gemm<0><<<ggrid(D1), 256, SMEM_SZ>>>(x,  W0, b0, r1, D1, D0);
    tc_gemm<0><<<ggrid(D2), 256, SMEM_SZ>>>(r1, W1, b1, r2, D2, D1);
    tc_gemm<0><<<ggrid(D3), 256, SMEM_SZ>>>(r2, W2, b2, r3, D3, D2);

    // ---- 20 PC inference steps
    for (int s = 0; s < NSTEPS; s++) {
        // errors: e_i = r_i - tanh(r_{i+1} @ W_i)   (B op = W_i^T, K-major)
        tc_gemm<1><<<ggrid(D2), 256, SMEM_SZ>>>(r3, wt2, r2, e2, D2, D3);
        tc_gemm<1><<<ggrid(D1), 256, SMEM_SZ>>>(r2, wt1, r1, e1, D1, D2);
        tc_gemm<1><<<ggrid(D0), 256, SMEM_SZ>>>(r1, wt0, x,  e0, D0, D1);
        // updates: r_i += LR * (e_{i-1} @ W_{i-1}^T - e_i)
        tc_gemm<2><<<ggrid(D1), 256, SMEM_SZ>>>(e0, W0, e1, r1, D1, D0);
        tc_gemm<2><<<ggrid(D2), 256, SMEM_SZ>>>(e1, W1, e2, r2, D2, D1);
        tc_gemm<2><<<ggrid(D3), 256, SMEM_SZ>>>(e2, W2, r3, r3, D3, D2);
    }

    // ---- final errors (for total_error)
    tc_gemm<1><<<ggrid(D2), 256, SMEM_SZ>>>(r3, wt2, r2, e2, D2, D3);
    tc_gemm<1><<<ggrid(D1), 256, SMEM_SZ>>>(r2, wt1, r1, e1, D1, D2);
    tc_gemm<1><<<ggrid(D0), 256, SMEM_SZ>>>(r1, wt0, x,  e0, D0, D1);

    // ---- output r3
    const int n_r3 = MB * D3;
    copy_k<<<(n_r3 / 4 + 255) / 256, 256>>>(r3, out, n_r3 / 4);

    // ---- total_error = 0.5 * (|e0|^2 + |e1|^2 + |e2|^2 + |r3|^2)
    sumsq_partial<<<1024, 256>>>(e0, (long long)MB * D0, part + 0);
    sumsq_partial<<<1024, 256>>>(e1, (long long)MB * D1, part + 1024);
    sumsq_partial<<<1024, 256>>>(e2, (long long)MB * D2, part + 2048);
    sumsq_partial<<<1024, 256>>>(r3, (long long)MB * D3, part + 3072);
    finalize_k<<<1, 256>>>(part, 4096, out + (out_size - 1));
}